// round 11
// baseline (speedup 1.0000x reference)
#include <cuda_runtime.h>
#include <math_constants.h>

#define NROWS 8192
#define DIM   64
#define KNN   32
#define MOUT  (NROWS - KNN)      // 8160 query rows
#define QT    32                 // queries per block (select)
#define CT    64                 // candidate tile rows (double-buffered)
#define SX    68                 // smem row stride in floats
#define NTHREADS 256
#define RQ    8                  // queries per block (refine)

__device__ float g_sq[NROWS];
__device__ int   g_idx[(size_t)MOUT * KNN];

#define CP_ASYNC16(dst, src) \
    asm volatile("cp.async.cg.shared.global [%0], [%1], 16;" :: "r"(dst), "l"(src))
#define CP_ASYNC4(dst, src) \
    asm volatile("cp.async.ca.shared.global [%0], [%1], 4;" :: "r"(dst), "l"(src))
#define CP_COMMIT() asm volatile("cp.async.commit_group;")
#define CP_WAIT(n)  asm volatile("cp.async.wait_group %0;" :: "n"(n))

__global__ void sq_kernel(const float* __restrict__ X) {
    int i = blockIdx.x * blockDim.x + threadIdx.x;
    if (i < NROWS) {
        const float4* x4 = (const float4*)(X + (size_t)i * DIM);
        float s = 0.f;
        #pragma unroll
        for (int t = 0; t < DIM / 4; ++t) {
            float4 v = x4[t];
            s += v.x * v.x + v.y * v.y + v.z * v.z + v.w * v.w;
        }
        g_sq[i] = s;
    }
}

// ---------------- phase 1: top-32 candidate selection ----------------
__global__ __launch_bounds__(NTHREADS, 2) void select_kernel(const float* __restrict__ X) {
    __shared__ float xs[2][CT * SX];
    __shared__ float qs[QT * DIM];
    __shared__ float sqc[2][CT];

    const int tid  = threadIdx.x;
    const int lane = tid & 31;
    const int warp = tid >> 5;
    const int b  = gridDim.x - 1 - blockIdx.x;
    const int qb = KNN + b * QT;

    const float4* X4 = (const float4*)X;

    // stage queries (plain loads; once per block)
    for (int idx = tid; idx < QT * (DIM / 4); idx += NTHREADS) {
        int row = idx >> 4, c = idx & 15;
        ((float4*)qs)[row * (DIM / 4) + c] = X4[(size_t)(qb + row) * (DIM / 4) + c];
    }

    float sqq[4];
    float ld[4];
    int   li[4];
    #pragma unroll
    for (int w = 0; w < 4; ++w) {
        sqq[w] = g_sq[qb + warp * 4 + w];
        ld[w]  = CUDART_INF_F;
        li[w]  = -1;
    }

    // per-thread staging geometry: 4 x 16B chunks per tile
    const int srow = tid >> 4;           // 0..15 (row within tile, +16 per step)
    const int scol = tid & 15;           // float4 column
    const unsigned xs0 = (unsigned)__cvta_generic_to_shared(&xs[0][0]);
    const unsigned xs1 = (unsigned)__cvta_generic_to_shared(&xs[1][0]);
    const unsigned sq0 = (unsigned)__cvta_generic_to_shared(&sqc[0][0]);
    const unsigned sq1 = (unsigned)__cvta_generic_to_shared(&sqc[1][0]);

    const int cand_end = qb + QT;
    const int ntiles   = (cand_end + CT - 1) / CT;

    // prologue: stage tile 0 into buf 0
    {
        const float* src = X + ((size_t)srow * DIM + scol * 4);
        unsigned dst = xs0 + ((unsigned)(srow * SX + scol * 4)) * 4u;
        #pragma unroll
        for (int i = 0; i < 4; ++i)
            CP_ASYNC16(dst + (unsigned)(16 * i * SX * 4), src + (size_t)16 * i * DIM);
        if (tid < CT) CP_ASYNC4(sq0 + 4u * tid, &g_sq[tid]);
        CP_COMMIT();
    }

    for (int s = 0; s < ntiles; ++s) {
        const int buf = s & 1;
        if (s + 1 < ntiles) {
            const int tb1 = (s + 1) * CT;
            const float* src = X + ((size_t)(tb1 + srow) * DIM + scol * 4);
            unsigned dst = (buf ? xs0 : xs1) + ((unsigned)(srow * SX + scol * 4)) * 4u;
            #pragma unroll
            for (int i = 0; i < 4; ++i)
                CP_ASYNC16(dst + (unsigned)(16 * i * SX * 4), src + (size_t)16 * i * DIM);
            if (tid < CT) CP_ASYNC4((buf ? sq0 : sq1) + 4u * tid, &g_sq[tb1 + tid]);
            CP_COMMIT();
            CP_WAIT(1);                 // tile s complete, s+1 may still fly
        } else {
            CP_WAIT(0);
        }
        __syncthreads();

        const int tb = s * CT;
        float acc[4][2];
        #pragma unroll
        for (int w = 0; w < 4; ++w)
            #pragma unroll
            for (int ch = 0; ch < 2; ++ch) acc[w][ch] = 0.f;

        #pragma unroll 4
        for (int d4 = 0; d4 < DIM / 4; ++d4) {
            float4 qv[4], cv[2];
            #pragma unroll
            for (int w = 0; w < 4; ++w)
                qv[w] = *(const float4*)&qs[(warp * 4 + w) * DIM + d4 * 4];
            #pragma unroll
            for (int ch = 0; ch < 2; ++ch)
                cv[ch] = *(const float4*)&xs[buf][(lane + 32 * ch) * SX + d4 * 4];
            #pragma unroll
            for (int w = 0; w < 4; ++w)
                #pragma unroll
                for (int ch = 0; ch < 2; ++ch) {
                    acc[w][ch] = fmaf(qv[w].x, cv[ch].x, acc[w][ch]);
                    acc[w][ch] = fmaf(qv[w].y, cv[ch].y, acc[w][ch]);
                    acc[w][ch] = fmaf(qv[w].z, cv[ch].z, acc[w][ch]);
                    acc[w][ch] = fmaf(qv[w].w, cv[ch].w, acc[w][ch]);
                }
        }

        #pragma unroll
        for (int ch = 0; ch < 2; ++ch) {
            const int   j  = tb + ch * 32 + lane;
            const float sc = sqc[buf][ch * 32 + lane];
            #pragma unroll
            for (int w = 0; w < 4; ++w) {
                const int r = qb + warp * 4 + w;
                float dist = (j < r) ? fmaxf(sqq[w] + sc - 2.f * acc[w][ch], 0.f)
                                     : CUDART_INF_F;
                float kd = __shfl_sync(0xffffffffu, ld[w], 31);
                int   ki = __shfl_sync(0xffffffffu, li[w], 31);
                unsigned hits = __ballot_sync(0xffffffffu,
                                              dist < kd || (dist == kd && j < ki));
                while (hits) {
                    int src = __ffs(hits) - 1;
                    hits &= hits - 1;
                    float dv = __shfl_sync(0xffffffffu, dist, src);
                    int   iv = tb + ch * 32 + src;
                    bool lt  = (ld[w] < dv) || (ld[w] == dv && li[w] < iv);
                    int  pos = __popc(__ballot_sync(0xffffffffu, lt));
                    if (pos < 32) {
                        float pd = __shfl_up_sync(0xffffffffu, ld[w], 1);
                        int   pi = __shfl_up_sync(0xffffffffu, li[w], 1);
                        if (lane == pos)      { ld[w] = dv; li[w] = iv; }
                        else if (lane > pos)  { ld[w] = pd; li[w] = pi; }
                    }
                }
            }
        }
        __syncthreads();   // compute done before buf is refilled next-next iter
    }

    #pragma unroll
    for (int w = 0; w < 4; ++w) {
        const size_t m = (size_t)(qb + warp * 4 + w - KNN);
        g_idx[m * KNN + lane] = li[w];
    }
}

// ---------------- phase 2: reference-rounding refine + sort ----------------
__device__ __forceinline__ float sq_tree_smem(const float* __restrict__ c) {
    float t[32];
    #pragma unroll
    for (int l = 0; l < 32; ++l)
        t[l] = __fadd_rn(__fmul_rn(c[l], c[l]), __fmul_rn(c[l + 32], c[l + 32]));
    #pragma unroll
    for (int l = 0; l < 16; ++l) t[l] = __fadd_rn(t[l], t[l + 16]);
    #pragma unroll
    for (int l = 0; l < 8; ++l)  t[l] = __fadd_rn(t[l], t[l + 8]);
    #pragma unroll
    for (int l = 0; l < 4; ++l)  t[l] = __fadd_rn(t[l], t[l + 4]);
    t[0] = __fadd_rn(t[0], t[2]);
    t[1] = __fadd_rn(t[1], t[3]);
    return __fadd_rn(t[0], t[1]);
}

__global__ __launch_bounds__(NTHREADS) void refine_kernel(const float* __restrict__ X,
                                                          void* __restrict__ out, int mode) {
    __shared__ float qs[RQ * DIM];

    const int tid  = threadIdx.x;
    const int lane = tid & 31;
    const int warp = tid >> 5;
    const size_t m = (size_t)blockIdx.x * RQ + warp;

    const float4* X4 = (const float4*)X;
    const int qrow0 = blockIdx.x * RQ + KNN;

    for (int idx = tid; idx < RQ * (DIM / 4); idx += NTHREADS) {
        int row = idx >> 4, c = idx & 15;
        ((float4*)qs)[row * (DIM / 4) + c] = X4[(size_t)(qrow0 + row) * (DIM / 4) + c];
    }
    __syncthreads();

    const float* qrow = &qs[warp * DIM];
    float sqr = sq_tree_smem(qrow);

    int jj = g_idx[m * KNN + lane];

    float cv[DIM];
    const float4* crow = X4 + (size_t)jj * (DIM / 4);
    #pragma unroll
    for (int t = 0; t < DIM / 4; ++t) {
        float4 v = __ldg(&crow[t]);
        cv[4 * t + 0] = v.x; cv[4 * t + 1] = v.y;
        cv[4 * t + 2] = v.z; cv[4 * t + 3] = v.w;
    }
    float sqj = sq_tree_smem(cv);

    float dot = 0.f;
    #pragma unroll
    for (int t = 0; t < DIM; ++t) dot = __fmaf_rn(qrow[t], cv[t], dot);

    float df = fmaxf(__fsub_rn(__fadd_rn(sqr, sqj), __fmul_rn(2.f, dot)), 0.f);

    #pragma unroll
    for (int k = 2; k <= 32; k <<= 1) {
        #pragma unroll
        for (int s = k >> 1; s > 0; s >>= 1) {
            float od = __shfl_xor_sync(0xffffffffu, df, s);
            int   oi = __shfl_xor_sync(0xffffffffu, jj, s);
            bool up    = ((lane & k) == 0);
            bool lower = ((lane & s) == 0);
            bool mlt   = (df < od) || (df == od && jj < oi);
            bool take  = (lower == up) ? !mlt : mlt;
            if (take) { df = od; jj = oi; }
        }
    }

    float* of = (float*)out;
    of[m * KNN + lane] = df;
    if (mode == 0) {
        of[(size_t)MOUT * KNN + m * KNN + lane] = (float)jj;
    } else if (mode == 2) {
        long long* oi = (long long*)((char*)out + (size_t)MOUT * KNN * sizeof(float));
        oi[m * KNN + lane] = (long long)jj;
    }
}

extern "C" void kernel_launch(void* const* d_in, const int* in_sizes, int n_in,
                              void* d_out, int out_size) {
    const float* X = (const float*)d_in[0];
    for (int i = 0; i < n_in; ++i) {
        if (in_sizes[i] == NROWS * DIM) { X = (const float*)d_in[i]; break; }
    }

    sq_kernel<<<NROWS / 256, 256>>>(X);
    select_kernel<<<MOUT / QT, NTHREADS>>>(X);

    const int MK = MOUT * KNN;
    int mode;
    if (out_size == MK)            mode = 1;
    else if (out_size == 2 * MK)   mode = 0;
    else                           mode = 2;
    refine_kernel<<<MOUT / RQ, NTHREADS>>>(X, d_out, mode);
}

// round 12
// speedup vs baseline: 1.0916x; 1.0916x over previous
#include <cuda_runtime.h>
#include <math_constants.h>

#define NROWS 8192
#define DIM   64
#define KNN   32
#define MOUT  (NROWS - KNN)      // 8160 query rows
#define QT    16                 // queries per block (select; 4 per warp)
#define CT    128                // candidate tile rows
#define SX    68                 // smem row stride in floats
#define NT_SEL 128               // select block size (4 warps)
#define NTHREADS 256
#define RQ    8                  // queries per block (refine)

__device__ float g_sq[NROWS];
__device__ int   g_idx[(size_t)MOUT * KNN];

__global__ void sq_kernel(const float* __restrict__ X) {
    int i = blockIdx.x * blockDim.x + threadIdx.x;
    if (i < NROWS) {
        const float4* x4 = (const float4*)(X + (size_t)i * DIM);
        float s = 0.f;
        #pragma unroll
        for (int t = 0; t < DIM / 4; ++t) {
            float4 v = x4[t];
            s += v.x * v.x + v.y * v.y + v.z * v.z + v.w * v.w;
        }
        g_sq[i] = s;
    }
}

// ---------------- phase 1: top-32 candidate selection ----------------
// 128-thread CTAs: regs/CTA = 128*166 ≈ 21K -> 3 CTAs/SM (12 warps), cap 170 avoids spills.
__global__ __launch_bounds__(NT_SEL, 3) void select_kernel(const float* __restrict__ X) {
    __shared__ float xs[CT * SX];
    __shared__ float qs[QT * DIM];
    __shared__ float sqc[CT];

    const int tid  = threadIdx.x;
    const int lane = tid & 31;
    const int warp = tid >> 5;
    const int b  = gridDim.x - 1 - blockIdx.x;
    const int qb = KNN + b * QT;

    const float4* X4 = (const float4*)X;

    for (int idx = tid; idx < QT * (DIM / 4); idx += NT_SEL) {
        int row = idx >> 4, c = idx & 15;
        ((float4*)qs)[row * (DIM / 4) + c] = X4[(size_t)(qb + row) * (DIM / 4) + c];
    }

    float sqq[4];
    float ld[4];
    int   li[4];
    #pragma unroll
    for (int w = 0; w < 4; ++w) {
        sqq[w] = g_sq[qb + warp * 4 + w];
        ld[w]  = CUDART_INF_F;
        li[w]  = -1;
    }

    const int cand_end = qb + QT;
    for (int tb = 0; tb < cand_end; tb += CT) {
        __syncthreads();
        for (int idx = tid; idx < CT * (DIM / 4); idx += NT_SEL) {
            int row = idx >> 4, c = idx & 15;
            *(float4*)&xs[row * SX + c * 4] = X4[(size_t)(tb + row) * (DIM / 4) + c];
        }
        if (tid < CT) sqc[tid] = g_sq[tb + tid];
        __syncthreads();

        float acc[4][4];
        #pragma unroll
        for (int w = 0; w < 4; ++w)
            #pragma unroll
            for (int ch = 0; ch < 4; ++ch) acc[w][ch] = 0.f;

        #pragma unroll 4
        for (int d4 = 0; d4 < DIM / 4; ++d4) {
            float4 qv[4], cv[4];
            #pragma unroll
            for (int w = 0; w < 4; ++w)
                qv[w] = *(const float4*)&qs[(warp * 4 + w) * DIM + d4 * 4];
            #pragma unroll
            for (int ch = 0; ch < 4; ++ch)
                cv[ch] = *(const float4*)&xs[(lane + 32 * ch) * SX + d4 * 4];
            #pragma unroll
            for (int w = 0; w < 4; ++w)
                #pragma unroll
                for (int ch = 0; ch < 4; ++ch) {
                    acc[w][ch] = fmaf(qv[w].x, cv[ch].x, acc[w][ch]);
                    acc[w][ch] = fmaf(qv[w].y, cv[ch].y, acc[w][ch]);
                    acc[w][ch] = fmaf(qv[w].z, cv[ch].z, acc[w][ch]);
                    acc[w][ch] = fmaf(qv[w].w, cv[ch].w, acc[w][ch]);
                }
        }

        #pragma unroll
        for (int ch = 0; ch < 4; ++ch) {
            const int   j  = tb + ch * 32 + lane;
            const float sc = sqc[ch * 32 + lane];
            #pragma unroll
            for (int w = 0; w < 4; ++w) {
                const int r = qb + warp * 4 + w;
                float dist = (j < r) ? fmaxf(sqq[w] + sc - 2.f * acc[w][ch], 0.f)
                                     : CUDART_INF_F;
                float kd = __shfl_sync(0xffffffffu, ld[w], 31);
                int   ki = __shfl_sync(0xffffffffu, li[w], 31);
                unsigned hits = __ballot_sync(0xffffffffu,
                                              dist < kd || (dist == kd && j < ki));
                while (hits) {
                    int src = __ffs(hits) - 1;
                    hits &= hits - 1;
                    float dv = __shfl_sync(0xffffffffu, dist, src);
                    int   iv = tb + ch * 32 + src;
                    bool lt  = (ld[w] < dv) || (ld[w] == dv && li[w] < iv);
                    int  pos = __popc(__ballot_sync(0xffffffffu, lt));
                    if (pos < 32) {
                        float pd = __shfl_up_sync(0xffffffffu, ld[w], 1);
                        int   pi = __shfl_up_sync(0xffffffffu, li[w], 1);
                        if (lane == pos)      { ld[w] = dv; li[w] = iv; }
                        else if (lane > pos)  { ld[w] = pd; li[w] = pi; }
                    }
                }
            }
        }
    }

    #pragma unroll
    for (int w = 0; w < 4; ++w) {
        const size_t m = (size_t)(qb + warp * 4 + w - KNN);
        g_idx[m * KNN + lane] = li[w];
    }
}

// ---------------- phase 2: reference-rounding refine + sort ----------------
__device__ __forceinline__ float sq_tree_smem(const float* __restrict__ c) {
    float t[32];
    #pragma unroll
    for (int l = 0; l < 32; ++l)
        t[l] = __fadd_rn(__fmul_rn(c[l], c[l]), __fmul_rn(c[l + 32], c[l + 32]));
    #pragma unroll
    for (int l = 0; l < 16; ++l) t[l] = __fadd_rn(t[l], t[l + 16]);
    #pragma unroll
    for (int l = 0; l < 8; ++l)  t[l] = __fadd_rn(t[l], t[l + 8]);
    #pragma unroll
    for (int l = 0; l < 4; ++l)  t[l] = __fadd_rn(t[l], t[l + 4]);
    t[0] = __fadd_rn(t[0], t[2]);
    t[1] = __fadd_rn(t[1], t[3]);
    return __fadd_rn(t[0], t[1]);
}

__global__ __launch_bounds__(NTHREADS) void refine_kernel(const float* __restrict__ X,
                                                          void* __restrict__ out, int mode) {
    __shared__ float qs[RQ * DIM];

    const int tid  = threadIdx.x;
    const int lane = tid & 31;
    const int warp = tid >> 5;
    const size_t m = (size_t)blockIdx.x * RQ + warp;

    const float4* X4 = (const float4*)X;
    const int qrow0 = blockIdx.x * RQ + KNN;

    for (int idx = tid; idx < RQ * (DIM / 4); idx += NTHREADS) {
        int row = idx >> 4, c = idx & 15;
        ((float4*)qs)[row * (DIM / 4) + c] = X4[(size_t)(qrow0 + row) * (DIM / 4) + c];
    }
    __syncthreads();

    const float* qrow = &qs[warp * DIM];
    float sqr = sq_tree_smem(qrow);

    int jj = g_idx[m * KNN + lane];

    float cv[DIM];
    const float4* crow = X4 + (size_t)jj * (DIM / 4);
    #pragma unroll
    for (int t = 0; t < DIM / 4; ++t) {
        float4 v = __ldg(&crow[t]);
        cv[4 * t + 0] = v.x; cv[4 * t + 1] = v.y;
        cv[4 * t + 2] = v.z; cv[4 * t + 3] = v.w;
    }
    float sqj = sq_tree_smem(cv);

    float dot = 0.f;
    #pragma unroll
    for (int t = 0; t < DIM; ++t) dot = __fmaf_rn(qrow[t], cv[t], dot);

    float df = fmaxf(__fsub_rn(__fadd_rn(sqr, sqj), __fmul_rn(2.f, dot)), 0.f);

    #pragma unroll
    for (int k = 2; k <= 32; k <<= 1) {
        #pragma unroll
        for (int s = k >> 1; s > 0; s >>= 1) {
            float od = __shfl_xor_sync(0xffffffffu, df, s);
            int   oi = __shfl_xor_sync(0xffffffffu, jj, s);
            bool up    = ((lane & k) == 0);
            bool lower = ((lane & s) == 0);
            bool mlt   = (df < od) || (df == od && jj < oi);
            bool take  = (lower == up) ? !mlt : mlt;
            if (take) { df = od; jj = oi; }
        }
    }

    float* of = (float*)out;
    of[m * KNN + lane] = df;
    if (mode == 0) {
        of[(size_t)MOUT * KNN + m * KNN + lane] = (float)jj;
    } else if (mode == 2) {
        long long* oi = (long long*)((char*)out + (size_t)MOUT * KNN * sizeof(float));
        oi[m * KNN + lane] = (long long)jj;
    }
}

extern "C" void kernel_launch(void* const* d_in, const int* in_sizes, int n_in,
                              void* d_out, int out_size) {
    const float* X = (const float*)d_in[0];
    for (int i = 0; i < n_in; ++i) {
        if (in_sizes[i] == NROWS * DIM) { X = (const float*)d_in[i]; break; }
    }

    sq_kernel<<<NROWS / 256, 256>>>(X);
    select_kernel<<<MOUT / QT, NT_SEL>>>(X);

    const int MK = MOUT * KNN;
    int mode;
    if (out_size == MK)            mode = 1;
    else if (out_size == 2 * MK)   mode = 0;
    else                           mode = 2;
    refine_kernel<<<MOUT / RQ, NTHREADS>>>(X, d_out, mode);
}

// round 13
// speedup vs baseline: 1.1694x; 1.0713x over previous
#include <cuda_runtime.h>
#include <math_constants.h>

#define NROWS 8192
#define DIM   64
#define KNN   32
#define MOUT  (NROWS - KNN)      // 8160 query rows
#define QT    16                 // queries per block (select; 4 per warp)
#define CT    128                // candidate tile rows
#define SX    68                 // smem row stride in floats
#define NT_SEL 128               // select block size (4 warps)

__device__ float g_sq[NROWS];

__global__ void sq_kernel(const float* __restrict__ X) {
    int i = blockIdx.x * blockDim.x + threadIdx.x;
    if (i < NROWS) {
        const float4* x4 = (const float4*)(X + (size_t)i * DIM);
        float s = 0.f;
        #pragma unroll
        for (int t = 0; t < DIM / 4; ++t) {
            float4 v = x4[t];
            s += v.x * v.x + v.y * v.y + v.z * v.z + v.w * v.w;
        }
        g_sq[i] = s;
    }
}

// reference-rounding tree sum-of-squares (phase 2)
__device__ __forceinline__ float sq_tree_smem(const float* __restrict__ c) {
    float t[32];
    #pragma unroll
    for (int l = 0; l < 32; ++l)
        t[l] = __fadd_rn(__fmul_rn(c[l], c[l]), __fmul_rn(c[l + 32], c[l + 32]));
    #pragma unroll
    for (int l = 0; l < 16; ++l) t[l] = __fadd_rn(t[l], t[l + 16]);
    #pragma unroll
    for (int l = 0; l < 8; ++l)  t[l] = __fadd_rn(t[l], t[l + 8]);
    #pragma unroll
    for (int l = 0; l < 4; ++l)  t[l] = __fadd_rn(t[l], t[l + 4]);
    t[0] = __fadd_rn(t[0], t[2]);
    t[1] = __fadd_rn(t[1], t[3]);
    return __fadd_rn(t[0], t[1]);
}

// ------------- fused: top-32 selection + reference-rounding refine -------------
__global__ __launch_bounds__(NT_SEL, 3) void knn_fused_kernel(const float* __restrict__ X,
                                                              void* __restrict__ out, int mode) {
    __shared__ float xs[CT * SX];
    __shared__ float qs[QT * DIM];
    __shared__ float sqc[CT];

    const int tid  = threadIdx.x;
    const int lane = tid & 31;
    const int warp = tid >> 5;
    const int b  = gridDim.x - 1 - blockIdx.x;
    const int qb = KNN + b * QT;

    const float4* X4 = (const float4*)X;

    for (int idx = tid; idx < QT * (DIM / 4); idx += NT_SEL) {
        int row = idx >> 4, c = idx & 15;
        ((float4*)qs)[row * (DIM / 4) + c] = X4[(size_t)(qb + row) * (DIM / 4) + c];
    }

    float sqq[4];
    float ld[4];
    int   li[4];
    #pragma unroll
    for (int w = 0; w < 4; ++w) {
        sqq[w] = g_sq[qb + warp * 4 + w];
        ld[w]  = CUDART_INF_F;
        li[w]  = -1;
    }

    // ---------------- phase 1: selection mainloop (identical to R12) ----------------
    const int cand_end = qb + QT;
    for (int tb = 0; tb < cand_end; tb += CT) {
        __syncthreads();
        for (int idx = tid; idx < CT * (DIM / 4); idx += NT_SEL) {
            int row = idx >> 4, c = idx & 15;
            *(float4*)&xs[row * SX + c * 4] = X4[(size_t)(tb + row) * (DIM / 4) + c];
        }
        if (tid < CT) sqc[tid] = g_sq[tb + tid];
        __syncthreads();

        float acc[4][4];
        #pragma unroll
        for (int w = 0; w < 4; ++w)
            #pragma unroll
            for (int ch = 0; ch < 4; ++ch) acc[w][ch] = 0.f;

        #pragma unroll 4
        for (int d4 = 0; d4 < DIM / 4; ++d4) {
            float4 qv[4], cv[4];
            #pragma unroll
            for (int w = 0; w < 4; ++w)
                qv[w] = *(const float4*)&qs[(warp * 4 + w) * DIM + d4 * 4];
            #pragma unroll
            for (int ch = 0; ch < 4; ++ch)
                cv[ch] = *(const float4*)&xs[(lane + 32 * ch) * SX + d4 * 4];
            #pragma unroll
            for (int w = 0; w < 4; ++w)
                #pragma unroll
                for (int ch = 0; ch < 4; ++ch) {
                    acc[w][ch] = fmaf(qv[w].x, cv[ch].x, acc[w][ch]);
                    acc[w][ch] = fmaf(qv[w].y, cv[ch].y, acc[w][ch]);
                    acc[w][ch] = fmaf(qv[w].z, cv[ch].z, acc[w][ch]);
                    acc[w][ch] = fmaf(qv[w].w, cv[ch].w, acc[w][ch]);
                }
        }

        #pragma unroll
        for (int ch = 0; ch < 4; ++ch) {
            const int   j  = tb + ch * 32 + lane;
            const float sc = sqc[ch * 32 + lane];
            #pragma unroll
            for (int w = 0; w < 4; ++w) {
                const int r = qb + warp * 4 + w;
                float dist = (j < r) ? fmaxf(sqq[w] + sc - 2.f * acc[w][ch], 0.f)
                                     : CUDART_INF_F;
                float kd = __shfl_sync(0xffffffffu, ld[w], 31);
                int   ki = __shfl_sync(0xffffffffu, li[w], 31);
                unsigned hits = __ballot_sync(0xffffffffu,
                                              dist < kd || (dist == kd && j < ki));
                while (hits) {
                    int src = __ffs(hits) - 1;
                    hits &= hits - 1;
                    float dv = __shfl_sync(0xffffffffu, dist, src);
                    int   iv = tb + ch * 32 + src;
                    bool lt  = (ld[w] < dv) || (ld[w] == dv && li[w] < iv);
                    int  pos = __popc(__ballot_sync(0xffffffffu, lt));
                    if (pos < 32) {
                        float pd = __shfl_up_sync(0xffffffffu, ld[w], 1);
                        int   pi = __shfl_up_sync(0xffffffffu, li[w], 1);
                        if (lane == pos)      { ld[w] = dv; li[w] = iv; }
                        else if (lane > pos)  { ld[w] = pd; li[w] = pi; }
                    }
                }
            }
        }
    }

    // ---------------- phase 2: refine epilogue (identical math to R12 refine) ----------------
    #pragma unroll
    for (int w = 0; w < 4; ++w) {
        const float* qrow = &qs[(warp * 4 + w) * DIM];
        float sqr = sq_tree_smem(qrow);

        int jj = li[w];                                // list always full (r >= KNN)

        float cv[DIM];
        const float4* crow = X4 + (size_t)jj * (DIM / 4);
        #pragma unroll
        for (int t = 0; t < DIM / 4; ++t) {
            float4 v = __ldg(&crow[t]);
            cv[4 * t + 0] = v.x; cv[4 * t + 1] = v.y;
            cv[4 * t + 2] = v.z; cv[4 * t + 3] = v.w;
        }
        float sqj = sq_tree_smem(cv);

        float dot = 0.f;
        #pragma unroll
        for (int t = 0; t < DIM; ++t) dot = __fmaf_rn(qrow[t], cv[t], dot);

        float df = fmaxf(__fsub_rn(__fadd_rn(sqr, sqj), __fmul_rn(2.f, dot)), 0.f);

        // bitonic sort across 32 lanes, ascending (df, jj)
        #pragma unroll
        for (int k = 2; k <= 32; k <<= 1) {
            #pragma unroll
            for (int s = k >> 1; s > 0; s >>= 1) {
                float od = __shfl_xor_sync(0xffffffffu, df, s);
                int   oi = __shfl_xor_sync(0xffffffffu, jj, s);
                bool up    = ((lane & k) == 0);
                bool lower = ((lane & s) == 0);
                bool mlt   = (df < od) || (df == od && jj < oi);
                bool take  = (lower == up) ? !mlt : mlt;
                if (take) { df = od; jj = oi; }
            }
        }

        const size_t m = (size_t)(qb + warp * 4 + w - KNN);
        float* of = (float*)out;
        of[m * KNN + lane] = df;
        if (mode == 0) {
            of[(size_t)MOUT * KNN + m * KNN + lane] = (float)jj;
        } else if (mode == 2) {
            long long* oi = (long long*)((char*)out + (size_t)MOUT * KNN * sizeof(float));
            oi[m * KNN + lane] = (long long)jj;
        }
    }
}

extern "C" void kernel_launch(void* const* d_in, const int* in_sizes, int n_in,
                              void* d_out, int out_size) {
    const float* X = (const float*)d_in[0];
    for (int i = 0; i < n_in; ++i) {
        if (in_sizes[i] == NROWS * DIM) { X = (const float*)d_in[i]; break; }
    }

    sq_kernel<<<NROWS / 256, 256>>>(X);

    const int MK = MOUT * KNN;
    int mode;
    if (out_size == MK)            mode = 1;
    else if (out_size == 2 * MK)   mode = 0;
    else                           mode = 2;
    knn_fused_kernel<<<MOUT / QT, NT_SEL>>>(X, d_out, mode);
}

// round 14
// speedup vs baseline: 1.1734x; 1.0034x over previous
#include <cuda_runtime.h>
#include <math_constants.h>

#define NROWS 8192
#define DIM   64
#define KNN   32
#define MOUT  (NROWS - KNN)      // 8160 query rows
#define QT    16                 // queries per block (select; 4 per warp)
#define CT    128                // candidate tile rows
#define SX    68                 // smem row stride in floats
#define NT_SEL 128               // select block size (4 warps)

__device__ float g_sq[NROWS];

__global__ void sq_kernel(const float* __restrict__ X) {
    int i = blockIdx.x * blockDim.x + threadIdx.x;
    if (i < NROWS) {
        const float4* x4 = (const float4*)(X + (size_t)i * DIM);
        float s = 0.f;
        #pragma unroll
        for (int t = 0; t < DIM / 4; ++t) {
            float4 v = x4[t];
            s += v.x * v.x + v.y * v.y + v.z * v.z + v.w * v.w;
        }
        g_sq[i] = s;
    }
}

// ascending full bitonic sort of (d,i) across 32 lanes, lex order
__device__ __forceinline__ void bsort32(float& d, int& i, int lane) {
    #pragma unroll
    for (int k = 2; k <= 32; k <<= 1) {
        #pragma unroll
        for (int s = k >> 1; s > 0; s >>= 1) {
            float od = __shfl_xor_sync(0xffffffffu, d, s);
            int   oi = __shfl_xor_sync(0xffffffffu, i, s);
            bool up    = ((lane & k) == 0);
            bool lower = ((lane & s) == 0);
            bool mlt   = (d < od) || (d == od && i < oi);
            bool take  = (lower == up) ? !mlt : mlt;
            if (take) { d = od; i = oi; }
        }
    }
}

// ascending cleanup of a bitonic 32-sequence (5 stages)
__device__ __forceinline__ void bmerge32(float& d, int& i, int lane) {
    #pragma unroll
    for (int s = 16; s > 0; s >>= 1) {
        float od = __shfl_xor_sync(0xffffffffu, d, s);
        int   oi = __shfl_xor_sync(0xffffffffu, i, s);
        bool lower = ((lane & s) == 0);
        bool mlt   = (d < od) || (d == od && i < oi);
        bool take  = lower ? !mlt : mlt;
        if (take) { d = od; i = oi; }
    }
}

// reference-rounding tree sum-of-squares (phase 2)
__device__ __forceinline__ float sq_tree_smem(const float* __restrict__ c) {
    float t[32];
    #pragma unroll
    for (int l = 0; l < 32; ++l)
        t[l] = __fadd_rn(__fmul_rn(c[l], c[l]), __fmul_rn(c[l + 32], c[l + 32]));
    #pragma unroll
    for (int l = 0; l < 16; ++l) t[l] = __fadd_rn(t[l], t[l + 16]);
    #pragma unroll
    for (int l = 0; l < 8; ++l)  t[l] = __fadd_rn(t[l], t[l + 8]);
    #pragma unroll
    for (int l = 0; l < 4; ++l)  t[l] = __fadd_rn(t[l], t[l + 4]);
    t[0] = __fadd_rn(t[0], t[2]);
    t[1] = __fadd_rn(t[1], t[3]);
    return __fadd_rn(t[0], t[1]);
}

// ------------- fused: top-32 selection + reference-rounding refine -------------
__global__ __launch_bounds__(NT_SEL, 3) void knn_fused_kernel(const float* __restrict__ X,
                                                              void* __restrict__ out, int mode) {
    __shared__ float xs[CT * SX];
    __shared__ float qs[QT * DIM];
    __shared__ float sqc[CT];

    const int tid  = threadIdx.x;
    const int lane = tid & 31;
    const int warp = tid >> 5;
    const int b  = gridDim.x - 1 - blockIdx.x;
    const int qb = KNN + b * QT;

    const float4* X4 = (const float4*)X;

    for (int idx = tid; idx < QT * (DIM / 4); idx += NT_SEL) {
        int row = idx >> 4, c = idx & 15;
        ((float4*)qs)[row * (DIM / 4) + c] = X4[(size_t)(qb + row) * (DIM / 4) + c];
    }

    float sqq[4];
    float ld[4], kd[4];
    int   li[4], ki[4];
    #pragma unroll
    for (int w = 0; w < 4; ++w) {
        sqq[w] = g_sq[qb + warp * 4 + w];
        ld[w]  = CUDART_INF_F;  kd[w] = CUDART_INF_F;
        li[w]  = -1;            ki[w] = 0x7fffffff;
    }

    const int cand_end = qb + QT;
    for (int tb = 0; tb < cand_end; tb += CT) {
        __syncthreads();
        for (int idx = tid; idx < CT * (DIM / 4); idx += NT_SEL) {
            int row = idx >> 4, c = idx & 15;
            *(float4*)&xs[row * SX + c * 4] = X4[(size_t)(tb + row) * (DIM / 4) + c];
        }
        if (tid < CT) sqc[tid] = g_sq[tb + tid];
        __syncthreads();

        float acc[4][4];
        #pragma unroll
        for (int w = 0; w < 4; ++w)
            #pragma unroll
            for (int ch = 0; ch < 4; ++ch) acc[w][ch] = 0.f;

        #pragma unroll 4
        for (int d4 = 0; d4 < DIM / 4; ++d4) {
            float4 qv[4], cv[4];
            #pragma unroll
            for (int w = 0; w < 4; ++w)
                qv[w] = *(const float4*)&qs[(warp * 4 + w) * DIM + d4 * 4];
            #pragma unroll
            for (int ch = 0; ch < 4; ++ch)
                cv[ch] = *(const float4*)&xs[(lane + 32 * ch) * SX + d4 * 4];
            #pragma unroll
            for (int w = 0; w < 4; ++w)
                #pragma unroll
                for (int ch = 0; ch < 4; ++ch) {
                    acc[w][ch] = fmaf(qv[w].x, cv[ch].x, acc[w][ch]);
                    acc[w][ch] = fmaf(qv[w].y, cv[ch].y, acc[w][ch]);
                    acc[w][ch] = fmaf(qv[w].z, cv[ch].z, acc[w][ch]);
                    acc[w][ch] = fmaf(qv[w].w, cv[ch].w, acc[w][ch]);
                }
        }

        #pragma unroll
        for (int ch = 0; ch < 4; ++ch) {
            const int   j  = tb + ch * 32 + lane;
            const float sc = sqc[ch * 32 + lane];
            #pragma unroll
            for (int w = 0; w < 4; ++w) {
                const int r = qb + warp * 4 + w;
                float dist = (j < r) ? fmaxf(sqq[w] + sc - 2.f * acc[w][ch], 0.f)
                                     : CUDART_INF_F;

                if (tb == 0 && ch == 0) {
                    // init: candidates 0..31 all satisfy j < r (r >= 32) -> sort into list
                    float d0 = dist; int i0 = j;
                    bsort32(d0, i0, lane);
                    ld[w] = d0; li[w] = i0;
                    kd[w] = __shfl_sync(0xffffffffu, d0, 31);
                    ki[w] = __shfl_sync(0xffffffffu, i0, 31);
                    continue;
                }

                unsigned hits = __ballot_sync(0xffffffffu,
                                              dist < kd[w] || (dist == kd[w] && j < ki[w]));
                if (!hits) continue;
                int nh = __popc(hits);

                if (nh >= 8) {
                    // bulk path: sort hit vector, reverse, lex-min with list, cleanup
                    bool ishit = (hits >> lane) & 1u;
                    float hd = ishit ? dist : CUDART_INF_F;
                    int   hi = ishit ? j    : 0x7fffffff;
                    bsort32(hd, hi, lane);
                    float rd = __shfl_xor_sync(0xffffffffu, hd, 31);
                    int   ri = __shfl_xor_sync(0xffffffffu, hi, 31);
                    bool keep = (ld[w] < rd) || (ld[w] == rd && li[w] < ri);
                    float nd = keep ? ld[w] : rd;
                    int   ni = keep ? li[w] : ri;
                    bmerge32(nd, ni, lane);
                    ld[w] = nd; li[w] = ni;
                } else {
                    while (hits) {
                        int src = __ffs(hits) - 1;
                        hits &= hits - 1;
                        float dv = __shfl_sync(0xffffffffu, dist, src);
                        int   iv = tb + ch * 32 + src;
                        bool lt  = (ld[w] < dv) || (ld[w] == dv && li[w] < iv);
                        int  pos = __popc(__ballot_sync(0xffffffffu, lt));
                        if (pos < 32) {
                            float pd = __shfl_up_sync(0xffffffffu, ld[w], 1);
                            int   pi = __shfl_up_sync(0xffffffffu, li[w], 1);
                            if (lane == pos)      { ld[w] = dv; li[w] = iv; }
                            else if (lane > pos)  { ld[w] = pd; li[w] = pi; }
                        }
                    }
                }
                kd[w] = __shfl_sync(0xffffffffu, ld[w], 31);
                ki[w] = __shfl_sync(0xffffffffu, li[w], 31);
            }
        }
    }

    // ---------------- phase 2: refine epilogue (identical math) ----------------
    #pragma unroll
    for (int w = 0; w < 4; ++w) {
        const float* qrow = &qs[(warp * 4 + w) * DIM];
        float sqr = sq_tree_smem(qrow);

        int jj = li[w];

        float cv[DIM];
        const float4* crow = X4 + (size_t)jj * (DIM / 4);
        #pragma unroll
        for (int t = 0; t < DIM / 4; ++t) {
            float4 v = __ldg(&crow[t]);
            cv[4 * t + 0] = v.x; cv[4 * t + 1] = v.y;
            cv[4 * t + 2] = v.z; cv[4 * t + 3] = v.w;
        }
        float sqj = sq_tree_smem(cv);

        float dot = 0.f;
        #pragma unroll
        for (int t = 0; t < DIM; ++t) dot = __fmaf_rn(qrow[t], cv[t], dot);

        float df = fmaxf(__fsub_rn(__fadd_rn(sqr, sqj), __fmul_rn(2.f, dot)), 0.f);

        bsort32(df, jj, lane);

        const size_t m = (size_t)(qb + warp * 4 + w - KNN);
        float* of = (float*)out;
        of[m * KNN + lane] = df;
        if (mode == 0) {
            of[(size_t)MOUT * KNN + m * KNN + lane] = (float)jj;
        } else if (mode == 2) {
            long long* oi = (long long*)((char*)out + (size_t)MOUT * KNN * sizeof(float));
            oi[m * KNN + lane] = (long long)jj;
        }
    }
}

extern "C" void kernel_launch(void* const* d_in, const int* in_sizes, int n_in,
                              void* d_out, int out_size) {
    const float* X = (const float*)d_in[0];
    for (int i = 0; i < n_in; ++i) {
        if (in_sizes[i] == NROWS * DIM) { X = (const float*)d_in[i]; break; }
    }

    sq_kernel<<<NROWS / 256, 256>>>(X);

    const int MK = MOUT * KNN;
    int mode;
    if (out_size == MK)            mode = 1;
    else if (out_size == 2 * MK)   mode = 0;
    else                           mode = 2;
    knn_fused_kernel<<<MOUT / QT, NT_SEL>>>(X, d_out, mode);
}